// round 10
// baseline (speedup 1.0000x reference)
#include <cuda_runtime.h>
#include <cuda_fp16.h>
#include <stdint.h>

// Problem constants (fixed by the dataset)
#define N_NODES 50000    // divisible by 8 -> clean 8-nodes-per-warp proj
#define IN_DIM  128
#define N_EDGES 500000   // divisible by 2 -> no tail in the edge kernel

#define EDGE_CTAS    64
#define EDGE_THREADS 1024
#define EDGE_UNITS   (N_EDGES / 2)                 // 250000 int2-edge units
#define EDGE_SLOTS   4                              // ceil(250000 / 65536)
#define TABLE_BYTES  (N_NODES * 4)                  // 50000 x half2 = 195.3 KB
#define BULK_CHUNKS  4
#define BULK_BYTES   (TABLE_BYTES / BULK_CHUNKS)    // 50000 B, 16B-multiple

// Packed per-node projections: g_pair[n] = (proj_src[n], proj_dst[n]) as half2.
__device__ __half2 g_pair[N_NODES];

// ---------------------------------------------------------------------------
// Kernel 1: node projection. EIGHT nodes per warp -> 8 independent LDG.128
// streams (MLP=8); at the HBM roofline (~7.3TB/s measured R8).
// ---------------------------------------------------------------------------
__global__ __launch_bounds__(256) void proj_kernel(const float* __restrict__ x,
                                                   const float* __restrict__ W) {
    const int warp_id = (blockIdx.x * blockDim.x + threadIdx.x) >> 5;
    const int lane    = threadIdx.x & 31;
    const int base    = warp_id * 8;
    if (base >= N_NODES) return;

    const float4 wa = reinterpret_cast<const float4*>(W)[lane];            // W[:128]
    const float4 wb = reinterpret_cast<const float4*>(W + IN_DIM)[lane];   // W[128:]

    float4 xv[8];
    #pragma unroll
    for (int i = 0; i < 8; i++)
        xv[i] = reinterpret_cast<const float4*>(x + (size_t)(base + i) * IN_DIM)[lane];

    float sa[8], sb[8];
    #pragma unroll
    for (int i = 0; i < 8; i++) {
        sa[i] = xv[i].x * wa.x + xv[i].y * wa.y + xv[i].z * wa.z + xv[i].w * wa.w;
        sb[i] = xv[i].x * wb.x + xv[i].y * wb.y + xv[i].z * wb.z + xv[i].w * wb.w;
    }

    #pragma unroll
    for (int off = 16; off > 0; off >>= 1) {
        #pragma unroll
        for (int i = 0; i < 8; i++) {
            sa[i] += __shfl_xor_sync(0xFFFFFFFFu, sa[i], off);
            sb[i] += __shfl_xor_sync(0xFFFFFFFFu, sb[i], off);
        }
    }

    if (lane == 0) {
        __half2 p[8];
        #pragma unroll
        for (int i = 0; i < 8; i++) p[i] = __floats2half2_rn(sa[i], sb[i]);
        reinterpret_cast<uint4*>(g_pair + base)[0] = *reinterpret_cast<uint4*>(p);
        reinterpret_cast<uint4*>(g_pair + base)[1] = *reinterpret_cast<uint4*>(p + 4);
    }
}

// ---------------------------------------------------------------------------
// Sigmoid with one MUFU op: sigmoid(x) = 0.5*tanh(x/2) + 0.5
// ---------------------------------------------------------------------------
__device__ __forceinline__ float sigmoid_tanh(float v) {
    float t;
    asm("tanh.approx.f32 %0, %1;" : "=f"(t) : "f"(0.5f * v));
    return fmaf(0.5f, t, 0.5f);
}

// ---------------------------------------------------------------------------
// Kernel 2: table staged via cp.async.bulk (TMA bulk copy, one thread issues
// 4 chunks -> zero per-warp issue cost, streams at the LTS cap), while ALL
// edge-stream data (<=4 units/thread = 12 LDGs, MLP=12) is prefetched into
// registers. After the mbarrier flips, only LDS gathers + tanh + STG remain.
// ---------------------------------------------------------------------------
__global__ __launch_bounds__(EDGE_THREADS, 1)
void edge_kernel(const int* __restrict__ edge_index,
                 const float* __restrict__ edge_weight,
                 const float* __restrict__ b,
                 float* __restrict__ out) {
    extern __shared__ __half2 s_tab[];           // 195.3 KB table
    __shared__ __align__(8) uint64_t s_mbar;     // staging mbarrier

    const int tid = threadIdx.x;
    const uint32_t mbar_a = (uint32_t)__cvta_generic_to_shared(&s_mbar);

    if (tid == 0) {
        asm volatile("mbarrier.init.shared.b64 [%0], 1;" :: "r"(mbar_a) : "memory");
    }
    __syncthreads();

    if (tid == 0) {
        asm volatile("mbarrier.arrive.expect_tx.shared.b64 _, [%0], %1;"
                     :: "r"(mbar_a), "r"((uint32_t)TABLE_BYTES) : "memory");
        const uint32_t s_base = (uint32_t)__cvta_generic_to_shared(s_tab);
        const char*    g_base = reinterpret_cast<const char*>(g_pair);
        #pragma unroll
        for (int c = 0; c < BULK_CHUNKS; c++) {
            asm volatile(
                "cp.async.bulk.shared::cta.global.mbarrier::complete_tx::bytes "
                "[%0], [%1], %2, [%3];"
                :: "r"(s_base + c * BULK_BYTES), "l"(g_base + c * BULK_BYTES),
                   "r"((uint32_t)BULK_BYTES), "r"(mbar_a) : "memory");
        }
    }

    // --- Prefetch the WHOLE edge stream into registers (overlaps staging) ---
    const int t0     = blockIdx.x * EDGE_THREADS + tid;
    const int stride = EDGE_CTAS * EDGE_THREADS;          // 65536
    int2 sv[EDGE_SLOTS], dv[EDGE_SLOTS]; float2 wv[EDGE_SLOTS];
    #pragma unroll
    for (int s = 0; s < EDGE_SLOTS; s++) {
        const int t = t0 + s * stride;
        if (t < EDGE_UNITS) {
            sv[s] = reinterpret_cast<const int2*>(edge_index)[t];
            dv[s] = reinterpret_cast<const int2*>(edge_index + N_EDGES)[t];
            wv[s] = reinterpret_cast<const float2*>(edge_weight)[t];
        }
    }
    const float bias = b[0];

    // --- Wait for the table (acquire: orders the LDS gathers below) ---
    {
        uint32_t done;
        asm volatile(
            "{\n\t.reg .pred p;\n\t"
            "mbarrier.try_wait.parity.acquire.cta.shared::cta.b64 p, [%1], 0;\n\t"
            "selp.b32 %0, 1, 0, p;\n\t}"
            : "=r"(done) : "r"(mbar_a) : "memory");
        while (!done) {
            asm volatile(
                "{\n\t.reg .pred p;\n\t"
                "mbarrier.try_wait.parity.acquire.cta.shared::cta.b64 p, [%1], 0, 0x989680;\n\t"
                "selp.b32 %0, 1, 0, p;\n\t}"
                : "=r"(done) : "r"(mbar_a) : "memory");
        }
    }

    // --- Gather + sigmoid + scale, all operands already in regs/smem ---
    #pragma unroll
    for (int s = 0; s < EDGE_SLOTS; s++) {
        const int t = t0 + s * stride;
        if (t < EDGE_UNITS) {
            const int i0 = min(max(sv[s].x, 0), N_NODES - 1);
            const int i1 = min(max(sv[s].y, 0), N_NODES - 1);
            const int j0 = min(max(dv[s].x, 0), N_NODES - 1);
            const int j1 = min(max(dv[s].y, 0), N_NODES - 1);

            const float ps0 = __low2float(s_tab[i0]),  ps1 = __low2float(s_tab[i1]);
            const float pd0 = __high2float(s_tab[j0]), pd1 = __high2float(s_tab[j1]);

            float2 r;
            r.x = wv[s].x * sigmoid_tanh(ps0 + pd0 + bias);
            r.y = wv[s].y * sigmoid_tanh(ps1 + pd1 + bias);
            reinterpret_cast<float2*>(out)[t] = r;
        }
    }
}

// ---------------------------------------------------------------------------
// Launch. Inputs (metadata order): x, edge_index, edge_weight, W, b.
// ---------------------------------------------------------------------------
extern "C" void kernel_launch(void* const* d_in, const int* in_sizes, int n_in,
                              void* d_out, int out_size) {
    const float* x  = (const float*)d_in[0];
    const int*   ei = (const int*)d_in[1];
    const float* ew = (const float*)d_in[2];
    const float* W  = (const float*)d_in[3];
    const float* b  = (const float*)d_in[4];
    float*       o  = (float*)d_out;

    // Opt-in to >48KB dynamic smem (idempotent host-side config, not captured)
    cudaFuncSetAttribute(edge_kernel,
                         cudaFuncAttributeMaxDynamicSharedMemorySize, TABLE_BYTES);

    // Kernel 1: eight nodes per warp -> 6250 warps
    {
        const int threads = 256;
        const int warps_per_block = threads / 32;
        const int node_groups = N_NODES / 8;                 // 6250
        const int blocks = (node_groups + warps_per_block - 1) / warps_per_block;
        proj_kernel<<<blocks, threads>>>(x, W);
    }
    // Kernel 2: bulk-staged smem-table gather kernel
    edge_kernel<<<EDGE_CTAS, EDGE_THREADS, TABLE_BYTES>>>(ei, ew, b, o);
}

// round 12
// speedup vs baseline: 1.0067x; 1.0067x over previous
#include <cuda_runtime.h>
#include <cuda_fp16.h>
#include <stdint.h>

// Problem constants (fixed by the dataset)
#define N_NODES 50000    // divisible by 8 -> clean 8-nodes-per-warp proj
#define IN_DIM  128
#define N_EDGES 500000   // divisible by 2 -> no tail in the edge kernel

#define CLUSTER_SZ   4
#define EDGE_CTAS    96                             // 24 clusters of 4
#define EDGE_THREADS 1024
#define EDGE_UNITS   (N_EDGES / 2)                  // 250000 int2-edge units
#define EDGE_SLOTS   3                              // ceil(250000 / 98304)
#define TABLE_BYTES  (N_NODES * 4)                  // 50000 x half2 = 195.3 KB
#define CHUNK_BYTES  (TABLE_BYTES / CLUSTER_SZ)     // 50000 B (16B multiple)

// Packed per-node projections: g_pair[n] = (proj_src[n], proj_dst[n]) as half2.
__device__ __half2 g_pair[N_NODES];

// ---------------------------------------------------------------------------
// Kernel 1: node projection. EIGHT nodes per warp -> 8 independent LDG.128
// streams (MLP=8); at the HBM roofline. Unchanged from R8/R10.
// ---------------------------------------------------------------------------
__global__ __launch_bounds__(256) void proj_kernel(const float* __restrict__ x,
                                                   const float* __restrict__ W) {
    const int warp_id = (blockIdx.x * blockDim.x + threadIdx.x) >> 5;
    const int lane    = threadIdx.x & 31;
    const int base    = warp_id * 8;
    if (base >= N_NODES) return;

    const float4 wa = reinterpret_cast<const float4*>(W)[lane];            // W[:128]
    const float4 wb = reinterpret_cast<const float4*>(W + IN_DIM)[lane];   // W[128:]

    float4 xv[8];
    #pragma unroll
    for (int i = 0; i < 8; i++)
        xv[i] = reinterpret_cast<const float4*>(x + (size_t)(base + i) * IN_DIM)[lane];

    float sa[8], sb[8];
    #pragma unroll
    for (int i = 0; i < 8; i++) {
        sa[i] = xv[i].x * wa.x + xv[i].y * wa.y + xv[i].z * wa.z + xv[i].w * wa.w;
        sb[i] = xv[i].x * wb.x + xv[i].y * wb.y + xv[i].z * wb.z + xv[i].w * wb.w;
    }

    #pragma unroll
    for (int off = 16; off > 0; off >>= 1) {
        #pragma unroll
        for (int i = 0; i < 8; i++) {
            sa[i] += __shfl_xor_sync(0xFFFFFFFFu, sa[i], off);
            sb[i] += __shfl_xor_sync(0xFFFFFFFFu, sb[i], off);
        }
    }

    if (lane == 0) {
        __half2 p[8];
        #pragma unroll
        for (int i = 0; i < 8; i++) p[i] = __floats2half2_rn(sa[i], sb[i]);
        reinterpret_cast<uint4*>(g_pair + base)[0] = *reinterpret_cast<uint4*>(p);
        reinterpret_cast<uint4*>(g_pair + base)[1] = *reinterpret_cast<uint4*>(p + 4);
    }
}

// ---------------------------------------------------------------------------
// Sigmoid with one MUFU op: sigmoid(x) = 0.5*tanh(x/2) + 0.5
// ---------------------------------------------------------------------------
__device__ __forceinline__ float sigmoid_tanh(float v) {
    float t;
    asm("tanh.approx.f32 %0, %1;" : "=f"(t) : "f"(0.5f * v));
    return fmaf(0.5f, t, 0.5f);
}

// ---------------------------------------------------------------------------
// Kernel 2: table staged via MULTICAST bulk copy across 4-CTA clusters.
// Each rank issues ONE 50000B chunk multicast to all 4 CTAs (cooperative
// slicing) -> L2 broadcast traffic drops 4x vs per-CTA staging (the R8/R10
// bottleneck per the cost model). Edge stream is register-prefetched under
// the staging; post-wait work is pure LDS gathers + tanh + STG.
// ---------------------------------------------------------------------------
__global__ __launch_bounds__(EDGE_THREADS, 1) __cluster_dims__(CLUSTER_SZ, 1, 1)
void edge_kernel(const int* __restrict__ edge_index,
                 const float* __restrict__ edge_weight,
                 const float* __restrict__ b,
                 float* __restrict__ out) {
    extern __shared__ __half2 s_tab[];           // 195.3 KB table
    __shared__ __align__(8) uint64_t s_mbar;     // staging mbarrier (same offset in all CTAs)

    const int tid = threadIdx.x;
    const uint32_t mbar_a = (uint32_t)__cvta_generic_to_shared(&s_mbar);

    if (tid == 0) {
        asm volatile("mbarrier.init.shared.b64 [%0], 1;" :: "r"(mbar_a) : "memory");
    }
    __syncthreads();

    // All cluster CTAs' mbarriers must be live before any multicast targets them.
    asm volatile("barrier.cluster.arrive.aligned;" ::: "memory");
    asm volatile("barrier.cluster.wait.aligned;"   ::: "memory");

    if (tid == 0) {
        // Expect the FULL table on our local barrier (4 partial complete_tx).
        asm volatile("mbarrier.arrive.expect_tx.shared.b64 _, [%0], %1;"
                     :: "r"(mbar_a), "r"((uint32_t)TABLE_BYTES) : "memory");
        uint32_t rank;
        asm("mov.u32 %0, %%cluster_ctarank;" : "=r"(rank));
        const uint32_t s_dst  = (uint32_t)__cvta_generic_to_shared(s_tab) + rank * CHUNK_BYTES;
        const char*    g_src  = reinterpret_cast<const char*>(g_pair) + rank * CHUNK_BYTES;
        const uint16_t mask   = (1u << CLUSTER_SZ) - 1u;   // 0xF
        asm volatile(
            "cp.async.bulk.shared::cluster.global.mbarrier::complete_tx::bytes"
            ".multicast::cluster [%0], [%1], %2, [%3], %4;"
            :: "r"(s_dst), "l"(g_src), "r"((uint32_t)CHUNK_BYTES),
               "r"(mbar_a), "h"(mask) : "memory");
    }

    // --- Prefetch the WHOLE edge stream into registers (overlaps staging) ---
    const int t0     = blockIdx.x * EDGE_THREADS + tid;
    const int stride = EDGE_CTAS * EDGE_THREADS;          // 98304
    int2 sv[EDGE_SLOTS], dv[EDGE_SLOTS]; float2 wv[EDGE_SLOTS];
    #pragma unroll
    for (int s = 0; s < EDGE_SLOTS; s++) {
        const int t = t0 + s * stride;
        if (t < EDGE_UNITS) {
            sv[s] = reinterpret_cast<const int2*>(edge_index)[t];
            dv[s] = reinterpret_cast<const int2*>(edge_index + N_EDGES)[t];
            wv[s] = reinterpret_cast<const float2*>(edge_weight)[t];
        }
    }
    const float bias = b[0];

    // --- Wait for the table (acquire: orders the LDS gathers below) ---
    {
        uint32_t done;
        asm volatile(
            "{\n\t.reg .pred p;\n\t"
            "mbarrier.try_wait.parity.acquire.cta.shared::cta.b64 p, [%1], 0;\n\t"
            "selp.b32 %0, 1, 0, p;\n\t}"
            : "=r"(done) : "r"(mbar_a) : "memory");
        while (!done) {
            asm volatile(
                "{\n\t.reg .pred p;\n\t"
                "mbarrier.try_wait.parity.acquire.cta.shared::cta.b64 p, [%1], 0, 0x989680;\n\t"
                "selp.b32 %0, 1, 0, p;\n\t}"
                : "=r"(done) : "r"(mbar_a) : "memory");
        }
    }

    // --- Gather + sigmoid + scale, all operands already in regs/smem ---
    #pragma unroll
    for (int s = 0; s < EDGE_SLOTS; s++) {
        const int t = t0 + s * stride;
        if (t < EDGE_UNITS) {
            const int i0 = min(max(sv[s].x, 0), N_NODES - 1);
            const int i1 = min(max(sv[s].y, 0), N_NODES - 1);
            const int j0 = min(max(dv[s].x, 0), N_NODES - 1);
            const int j1 = min(max(dv[s].y, 0), N_NODES - 1);

            const float ps0 = __low2float(s_tab[i0]),  ps1 = __low2float(s_tab[i1]);
            const float pd0 = __high2float(s_tab[j0]), pd1 = __high2float(s_tab[j1]);

            float2 r;
            r.x = wv[s].x * sigmoid_tanh(ps0 + pd0 + bias);
            r.y = wv[s].y * sigmoid_tanh(ps1 + pd1 + bias);
            reinterpret_cast<float2*>(out)[t] = r;
        }
    }

    // No CTA may exit while a peer's multicast targeting its SMEM is in flight.
    asm volatile("barrier.cluster.arrive.aligned;" ::: "memory");
    asm volatile("barrier.cluster.wait.aligned;"   ::: "memory");
}

// ---------------------------------------------------------------------------
// Launch. Inputs (metadata order): x, edge_index, edge_weight, W, b.
// ---------------------------------------------------------------------------
extern "C" void kernel_launch(void* const* d_in, const int* in_sizes, int n_in,
                              void* d_out, int out_size) {
    const float* x  = (const float*)d_in[0];
    const int*   ei = (const int*)d_in[1];
    const float* ew = (const float*)d_in[2];
    const float* W  = (const float*)d_in[3];
    const float* b  = (const float*)d_in[4];
    float*       o  = (float*)d_out;

    // Opt-in to >48KB dynamic smem (idempotent host-side config, not captured)
    cudaFuncSetAttribute(edge_kernel,
                         cudaFuncAttributeMaxDynamicSharedMemorySize, TABLE_BYTES);

    // Kernel 1: eight nodes per warp -> 6250 warps
    {
        const int threads = 256;
        const int warps_per_block = threads / 32;
        const int node_groups = N_NODES / 8;                 // 6250
        const int blocks = (node_groups + warps_per_block - 1) / warps_per_block;
        proj_kernel<<<blocks, threads>>>(x, W);
    }
    // Kernel 2: clustered, multicast-staged smem-table gather kernel
    edge_kernel<<<EDGE_CTAS, EDGE_THREADS, TABLE_BYTES>>>(ei, ew, b, o);
}